// round 3
// baseline (speedup 1.0000x reference)
#include <cuda_runtime.h>

// ---------------------------------------------------------------------------
// DECOLA Stage2 assigner.
// Inputs (metadata order):
//   0: pred_logits_match (B,N,1) f32   -- unused (sigmoid discarded in ref)
//   1: pred_boxes        (B,N,4) f32   -- unused
//   2: init_reference    (B,N,4) f32   -- proposals (cxcywh)
//   3: prompt_inds       (B,N)   i32
//   4: gt_labels         (B,M)   i32
//   5: gt_boxes          (B,M,4) f32   -- cxcywh
//   6: max_k             scalar  i32   -- k derived from out_size instead
// Output: concat(rows, cols, valid, sel_iou) each (B,M,k), as float32.
// ---------------------------------------------------------------------------

#define BB      16          // batch (fixed shape for this problem)
#define MAX_BN  49152
#define MAX_BM  8192
#define MAXM    512
#define TOPK    4
#define IMAXI   0x7fffffff

__device__ float4 g_pxy[MAX_BN];      // proposal xyxy
__device__ float  g_pa [MAX_BN];      // proposal area
__device__ float4 g_gxy[MAX_BM];      // gt xyxy
__device__ float  g_ga [MAX_BM];      // gt area
__device__ float  g_gmax[MAX_BM];     // per-gt row max of miou
__device__ float  g_topv[MAX_BM * TOPK];
__device__ int    g_topi[MAX_BM * TOPK];
__device__ int    g_cnt [MAX_BM];

// IoU built from explicit round-to-nearest intrinsics so that the row pass
// and the column pass produce BITWISE-identical values (lq needs v == gmax).
__device__ __forceinline__ float iou_fn(float4 g, float ga, float4 p, float pa) {
    float x0 = fmaxf(g.x, p.x);
    float y0 = fmaxf(g.y, p.y);
    float x1 = fminf(g.z, p.z);
    float y1 = fminf(g.w, p.w);
    float w  = fmaxf(__fsub_rn(x1, x0), 0.0f);
    float h  = fmaxf(__fsub_rn(y1, y0), 0.0f);
    float it = __fmul_rn(w, h);
    float un = __fsub_rn(__fadd_rn(ga, pa), it);
    return __fdiv_rn(it, fmaxf(un, 1e-9f));
}

// Insert (v,i) into a 4-entry list sorted by (value desc, index asc).
// Matches jax.lax.top_k stability (lower index first among equal values).
__device__ __forceinline__ void ins4(float v, int i, float tv[TOPK], int ti[TOPK]) {
    if (v > tv[3] || (v == tv[3] && i < ti[3])) {
        if (v > tv[2] || (v == tv[2] && i < ti[2])) {
            tv[3] = tv[2]; ti[3] = ti[2];
            if (v > tv[1] || (v == tv[1] && i < ti[1])) {
                tv[2] = tv[1]; ti[2] = ti[1];
                if (v > tv[0] || (v == tv[0] && i < ti[0])) {
                    tv[1] = tv[0]; ti[1] = ti[0];
                    tv[0] = v;     ti[0] = i;
                } else { tv[1] = v; ti[1] = i; }
            } else { tv[2] = v; ti[2] = i; }
        } else { tv[3] = v; ti[3] = i; }
    }
}

// ---------------- Kernel 0: cxcywh -> xyxy + area, once ----------------
__global__ void k_prep(const float4* __restrict__ props,
                       const float4* __restrict__ gts,
                       int BN, int BM) {
    int idx = blockIdx.x * blockDim.x + threadIdx.x;
    if (idx < BN) {
        float4 c = props[idx];
        float4 x;
        x.x = c.x - 0.5f * c.z; x.y = c.y - 0.5f * c.w;
        x.z = c.x + 0.5f * c.z; x.w = c.y + 0.5f * c.w;
        g_pxy[idx] = x;
        g_pa [idx] = __fmul_rn(__fsub_rn(x.z, x.x), __fsub_rn(x.w, x.y));
    } else if (idx < BN + BM) {
        int j = idx - BN;
        float4 c = gts[j];
        float4 x;
        x.x = c.x - 0.5f * c.z; x.y = c.y - 0.5f * c.w;
        x.z = c.x + 0.5f * c.z; x.w = c.y + 0.5f * c.w;
        g_gxy[j] = x;
        g_ga [j] = __fmul_rn(__fsub_rn(x.z, x.x), __fsub_rn(x.w, x.y));
    }
}

// ------------- Kernel 1: per (b,m) GT row: gmax + stable top-4 -------------
// One block per GT row. Only matched pairs (~1/80) compute IoU.
__global__ __launch_bounds__(128) void k_rows(
        const int* __restrict__ pinds,
        const int* __restrict__ glabels,
        int N, int M) {
    int b  = blockIdx.y;
    int m  = blockIdx.x;
    int bm = b * M + m;
    int label = glabels[bm];
    float4 g = g_gxy[bm];
    float ga = g_ga[bm];

    const int*    pi = pinds + b * N;
    const float4* pp = g_pxy + b * N;
    const float*  pa = g_pa  + b * N;

    float tv[TOPK] = {-1.f, -1.f, -1.f, -1.f};
    int   ti[TOPK] = {IMAXI, IMAXI, IMAXI, IMAXI};

    for (int n = threadIdx.x; n < N; n += 128) {
        if (pi[n] == label) {
            float v = iou_fn(g, ga, pp[n], pa[n]);
            ins4(v, n, tv, ti);            // ascending n -> stable
        }
    }

    __shared__ float sv[128 * TOPK];
    __shared__ int   si[128 * TOPK];
    __shared__ float rv[4 * TOPK];
    __shared__ int   ri[4 * TOPK];

    int t = threadIdx.x;
#pragma unroll
    for (int j = 0; j < TOPK; j++) { sv[t * TOPK + j] = tv[j]; si[t * TOPK + j] = ti[j]; }
    __syncthreads();

    if (t < 4) {
        float av[TOPK] = {-1.f, -1.f, -1.f, -1.f};
        int   ai[TOPK] = {IMAXI, IMAXI, IMAXI, IMAXI};
        int base = t * 128;                // 32 threads' worth of candidates
        for (int c = base; c < base + 128; c++) ins4(sv[c], si[c], av, ai);
#pragma unroll
        for (int j = 0; j < TOPK; j++) { rv[t * TOPK + j] = av[j]; ri[t * TOPK + j] = ai[j]; }
    }
    __syncthreads();

    if (t == 0) {
        float av[TOPK] = {-1.f, -1.f, -1.f, -1.f};
        int   ai[TOPK] = {IMAXI, IMAXI, IMAXI, IMAXI};
        for (int c = 0; c < 4 * TOPK; c++) ins4(rv[c], ri[c], av, ai);
        g_gmax[bm] = av[0];                // -1 when row has no match (== ref NEG)
#pragma unroll
        for (int j = 0; j < TOPK; j++) {
            g_topv[bm * TOPK + j] = av[j];
            g_topi[bm * TOPK + j] = ai[j];
        }
        g_cnt[bm] = 0;                     // zero counts for kernel 2
    }
}

// ------------- Kernel 2: per proposal column: best_gt, pos, counts -------------
__global__ __launch_bounds__(256) void k_cols(
        const int* __restrict__ pinds,
        const int* __restrict__ glabels,
        int N, int M) {
    __shared__ int    sl [MAXM];
    __shared__ float  sgm[MAXM];
    __shared__ float4 sg [MAXM];
    __shared__ float  sga[MAXM];

    int b = blockIdx.y;
    for (int i = threadIdx.x; i < M; i += blockDim.x) {
        int bm = b * M + i;
        sl [i] = glabels[bm];
        sgm[i] = g_gmax[bm];
        sg [i] = g_gxy[bm];
        sga[i] = g_ga[bm];
    }
    __syncthreads();

    int n = blockIdx.x * blockDim.x + threadIdx.x;
    if (n >= N) return;

    int   pv = pinds[b * N + n];
    float4 p = g_pxy[b * N + n];
    float pa = g_pa [b * N + n];

    float best = -2.0f;   // below NEG so first -1/any value wins, bg defaults to 0
    int   bg   = 0;
    bool  lq   = false;

    for (int m = 0; m < M; m++) {
        if (sl[m] == pv) {
            float v = iou_fn(sg[m], sga[m], p, pa);
            if (v > best) { best = v; bg = m; }     // strict > : first argmax (JAX)
            lq = lq || (v == sgm[m]);               // bitwise match vs k_rows
        }
    }
    // pos = valid_prop & (best_iou >= 0.6 | lq); both branches imply a match.
    if (best >= 0.6f || lq) atomicAdd(&g_cnt[b * M + bg], 1);
}

// ------------- Kernel 3: epilogue — write rows | cols | valid | sel_iou -------------
__global__ void k_out(float* __restrict__ out, int BM, int M, int K) {
    int bm = blockIdx.x * blockDim.x + threadIdx.x;
    if (bm >= BM) return;
    int m    = bm % M;
    int take = min(g_cnt[bm], K);
    int base = bm * K;
    int S    = BM * K;
    for (int j = 0; j < K; j++) {
        bool val = (j < take);
        float r  = val ? (float)g_topi[bm * TOPK + j] : -1.0f;
        float cc = val ? (float)m                     : -1.0f;
        float vi = val ? g_topv[bm * TOPK + j]        : 0.0f;
        out[         base + j] = r;
        out[    S +  base + j] = cc;
        out[2 * S +  base + j] = val ? 1.0f : 0.0f;
        out[3 * S +  base + j] = vi;
    }
}

// ---------------------------------------------------------------------------
extern "C" void kernel_launch(void* const* d_in, const int* in_sizes, int n_in,
                              void* d_out, int out_size) {
    const float4* props   = (const float4*)d_in[2];   // init_reference (B,N,4)
    const int*    pinds   = (const int*)   d_in[3];   // prompt_inds    (B,N)
    const int*    glabels = (const int*)   d_in[4];   // gt_labels      (B,M)
    const float4* gts     = (const float4*)d_in[5];   // gt_boxes       (B,M,4)

    const int B  = BB;
    int BN = in_sizes[3];
    int BM = in_sizes[4];
    int N  = BN / B;
    int M  = BM / B;
    int K  = out_size / (4 * BM);
    if (K > TOPK) K = TOPK;
    if (K < 1)    K = 1;

    int tot = BN + BM;
    k_prep<<<(tot + 255) / 256, 256>>>(props, gts, BN, BM);
    k_rows<<<dim3(M, B), 128>>>(pinds, glabels, N, M);
    k_cols<<<dim3((N + 255) / 256, B), 256>>>(pinds, glabels, N, M);
    k_out <<<(BM + 255) / 256, 256>>>((float*)d_out, BM, M, K);
}

// round 5
// speedup vs baseline: 4.2936x; 4.2936x over previous
#include <cuda_runtime.h>

// ---------------------------------------------------------------------------
// DECOLA Stage2 assigner — label-bucketed version.
// match = (gt_label == prompt_ind) has density 1/L (~1/80), so we counting-sort
// proposals and GTs into per-(batch,label) buckets once, then both passes scan
// only matching pairs (~180k IoUs instead of 14.4M label tests per pass).
//
// Inputs (metadata order):
//   0: pred_logits_match (B,N,1) f32   -- unused
//   1: pred_boxes        (B,N,4) f32   -- unused
//   2: init_reference    (B,N,4) f32   -- proposals (cxcywh)
//   3: prompt_inds       (B,N)   i32
//   4: gt_labels         (B,M)   i32
//   5: gt_boxes          (B,M,4) f32
//   6: max_k             scalar  i32   (k derived from out_size)
// Output: concat(rows, cols, valid, sel_iou) each (B,M,k), float32.
// ---------------------------------------------------------------------------

#define BB      16            // batch (fixed for this problem)
#define NL      128           // label slots (L=80, padded)
#define PCAP    256           // proposal bucket capacity (mean 37.5)
#define GCAP    64            // gt bucket capacity (mean 3.75)
#define NBK     (BB * NL)     // 2048 buckets
#define MAX_BN  49152
#define MAX_BM  8192
#define TOPK    4
#define IMAXI   0x7fffffff

// proposal data in original order (for column pass, coalesced by n)
__device__ float4 g_pxy[MAX_BN];
__device__ float  g_pa [MAX_BN];
// gt data in original order (for row pass)
__device__ float4 g_gxy[MAX_BM];
__device__ float  g_ga [MAX_BM];
// per-(b,label) proposal buckets (for row pass)
__device__ int    d_pcnt[NBK];
__device__ float4 p_bx[NBK * PCAP];
__device__ float  p_ba[NBK * PCAP];
__device__ int    p_bi[NBK * PCAP];
// per-(b,label) gt buckets (for column pass)
__device__ int    d_gcnt[NBK];
__device__ float4 gt_bx[NBK * GCAP];
__device__ float  gt_ba[NBK * GCAP];
__device__ int    gt_bm[NBK * GCAP];
// row-pass results
__device__ float  g_gmax[MAX_BM];
__device__ float  g_topv[MAX_BM * TOPK];
__device__ int    g_topi[MAX_BM * TOPK];
__device__ int    g_cnt [MAX_BM];

// IoU from explicit _rn intrinsics so row pass and column pass are
// BITWISE identical (lq needs v == gmax). Inputs are stored copies of
// identical bits, and all ops here are symmetric/deterministic.
__device__ __forceinline__ float iou_fn(float4 g, float ga, float4 p, float pa) {
    float x0 = fmaxf(g.x, p.x);
    float y0 = fmaxf(g.y, p.y);
    float x1 = fminf(g.z, p.z);
    float y1 = fminf(g.w, p.w);
    float w  = fmaxf(__fsub_rn(x1, x0), 0.0f);
    float h  = fmaxf(__fsub_rn(y1, y0), 0.0f);
    float it = __fmul_rn(w, h);
    float un = __fsub_rn(__fadd_rn(ga, pa), it);
    return __fdiv_rn(it, fmaxf(un, 1e-9f));
}

// Insert (v,i) into 4-entry list sorted by (value desc, index asc).
// Strict total order (indices distinct) -> result independent of insert order,
// and matches jax.lax.top_k stability.
__device__ __forceinline__ void ins4(float v, int i, float tv[TOPK], int ti[TOPK]) {
    if (v > tv[3] || (v == tv[3] && i < ti[3])) {
        if (v > tv[2] || (v == tv[2] && i < ti[2])) {
            tv[3] = tv[2]; ti[3] = ti[2];
            if (v > tv[1] || (v == tv[1] && i < ti[1])) {
                tv[2] = tv[1]; ti[2] = ti[1];
                if (v > tv[0] || (v == tv[0] && i < ti[0])) {
                    tv[1] = tv[0]; ti[1] = ti[0];
                    tv[0] = v;     ti[0] = i;
                } else { tv[1] = v; ti[1] = i; }
            } else { tv[2] = v; ti[2] = i; }
        } else { tv[3] = v; ti[3] = i; }
    }
}

__device__ __forceinline__ float4 cxcywh_to_xyxy(float4 c) {
    float4 x;
    x.x = c.x - 0.5f * c.z; x.y = c.y - 0.5f * c.w;
    x.z = c.x + 0.5f * c.z; x.w = c.y + 0.5f * c.w;
    return x;
}

// ---------------- Kernel 0: zero counters ----------------
__global__ void k_zero(int BM) {
    int i = blockIdx.x * blockDim.x + threadIdx.x;
    if (i < NBK) { d_pcnt[i] = 0; d_gcnt[i] = 0; }
    if (i < BM)  g_cnt[i] = 0;
}

// ---------------- Kernel 1: convert + bucket-scatter ----------------
__global__ void k_build(const float4* __restrict__ props,
                        const float4* __restrict__ gts,
                        const int* __restrict__ pinds,
                        const int* __restrict__ glabels,
                        int BN, int BM, int N, int M) {
    int idx = blockIdx.x * blockDim.x + threadIdx.x;
    if (idx < BN) {
        float4 x = cxcywh_to_xyxy(props[idx]);
        float  a = __fmul_rn(__fsub_rn(x.z, x.x), __fsub_rn(x.w, x.y));
        g_pxy[idx] = x;
        g_pa [idx] = a;
        int b  = idx / N;
        int bk = b * NL + pinds[idx];
        int s  = atomicAdd(&d_pcnt[bk], 1);
        if (s < PCAP) {
            p_bx[bk * PCAP + s] = x;
            p_ba[bk * PCAP + s] = a;
            p_bi[bk * PCAP + s] = idx - b * N;
        }
    } else if (idx < BN + BM) {
        int j = idx - BN;
        float4 x = cxcywh_to_xyxy(gts[j]);
        float  a = __fmul_rn(__fsub_rn(x.z, x.x), __fsub_rn(x.w, x.y));
        g_gxy[j] = x;
        g_ga [j] = a;
        int b  = j / M;
        int bk = b * NL + glabels[j];
        int s  = atomicAdd(&d_gcnt[bk], 1);
        if (s < GCAP) {
            gt_bx[bk * GCAP + s] = x;
            gt_ba[bk * GCAP + s] = a;
            gt_bm[bk * GCAP + s] = j - b * M;
        }
    }
}

// -------- Kernel 2: one warp per GT row: gmax + stable top-4 --------
__global__ __launch_bounds__(256) void k_rows(
        const int* __restrict__ glabels, int M, int BM) {
    int w = (blockIdx.x * blockDim.x + threadIdx.x) >> 5;
    if (w >= BM) return;                 // uniform per warp
    int lane = threadIdx.x & 31;
    int b  = w / M;
    int bm = w;
    int bk = b * NL + glabels[bm];
    int cnt  = min(d_pcnt[bk], PCAP);
    int base = bk * PCAP;

    float4 g = g_gxy[bm];
    float ga = g_ga[bm];

    float tv[TOPK] = {-1.f, -1.f, -1.f, -1.f};
    int   ti[TOPK] = {IMAXI, IMAXI, IMAXI, IMAXI};

    for (int e = lane; e < cnt; e += 32) {
        float v = iou_fn(g, ga, p_bx[base + e], p_ba[base + e]);
        ins4(v, p_bi[base + e], tv, ti);
    }

    // butterfly merge of per-lane top-4 lists -> all lanes hold global top-4
#pragma unroll
    for (int off = 16; off > 0; off >>= 1) {
        float ov[TOPK]; int oi[TOPK];
#pragma unroll
        for (int j = 0; j < TOPK; j++) {
            ov[j] = __shfl_xor_sync(0xffffffffu, tv[j], off);
            oi[j] = __shfl_xor_sync(0xffffffffu, ti[j], off);
        }
#pragma unroll
        for (int j = 0; j < TOPK; j++) ins4(ov[j], oi[j], tv, ti);
    }

    if (lane == 0) {
        g_gmax[bm] = tv[0];              // -1 when no matched proposal (== ref NEG)
#pragma unroll
        for (int j = 0; j < TOPK; j++) {
            g_topv[bm * TOPK + j] = tv[j];
            g_topi[bm * TOPK + j] = ti[j];
        }
    }
}

// -------- Kernel 3: one thread per proposal: best_gt, pos, counts --------
__global__ __launch_bounds__(256) void k_cols(
        const int* __restrict__ pinds, int N, int M) {
    int b = blockIdx.y;
    int n = blockIdx.x * blockDim.x + threadIdx.x;
    if (n >= N) return;

    int    pv = pinds[b * N + n];
    float4 p  = g_pxy[b * N + n];
    float  pa = g_pa [b * N + n];

    int bk   = b * NL + pv;
    int cnt  = min(d_gcnt[bk], GCAP);
    int base = bk * GCAP;

    float best = -2.0f;
    int   bg   = IMAXI;
    bool  lq   = false;

    for (int e = 0; e < cnt; e++) {
        float v = iou_fn(gt_bx[base + e], gt_ba[base + e], p, pa);
        int   m = gt_bm[base + e];
        // lexicographic (v desc, m asc) == JAX first-index argmax over matched
        // entries; unmatched rows are -1 < iou >= 0, never the argmax when a
        // match exists, and pos=false when none exists.
        if (v > best || (v == best && m < bg)) { best = v; bg = m; }
        lq = lq || (v == g_gmax[b * M + m]);   // bitwise vs k_rows
    }
    if (best >= 0.6f || lq) atomicAdd(&g_cnt[b * M + bg], 1);
}

// -------- Kernel 4: epilogue — rows | cols | valid | sel_iou --------
__global__ void k_out(float* __restrict__ out, int BM, int M, int K) {
    int e = blockIdx.x * blockDim.x + threadIdx.x;
    if (e >= BM * K) return;
    int bm = e / K;
    int j  = e - bm * K;
    int m  = bm % M;
    bool val = j < min(g_cnt[bm], K);
    int  S   = BM * K;
    out[        e] = val ? (float)g_topi[bm * TOPK + j] : -1.0f;
    out[    S + e] = val ? (float)m                     : -1.0f;
    out[2 * S + e] = val ? 1.0f : 0.0f;
    out[3 * S + e] = val ? g_topv[bm * TOPK + j]        : 0.0f;
}

// ---------------------------------------------------------------------------
extern "C" void kernel_launch(void* const* d_in, const int* in_sizes, int n_in,
                              void* d_out, int out_size) {
    const float4* props   = (const float4*)d_in[2];
    const int*    pinds   = (const int*)   d_in[3];
    const int*    glabels = (const int*)   d_in[4];
    const float4* gts     = (const float4*)d_in[5];

    const int B  = BB;
    int BN = in_sizes[3];
    int BM = in_sizes[4];
    int N  = BN / B;
    int M  = BM / B;
    int K  = out_size / (4 * BM);
    if (K > TOPK) K = TOPK;
    if (K < 1)    K = 1;

    int zN = (NBK > BM ? NBK : BM);
    k_zero <<<(zN + 255) / 256, 256>>>(BM);
    k_build<<<(BN + BM + 255) / 256, 256>>>(props, gts, pinds, glabels, BN, BM, N, M);
    k_rows <<<(BM * 32 + 255) / 256, 256>>>(glabels, M, BM);
    k_cols <<<dim3((N + 255) / 256, B), 256>>>(pinds, N, M);
    k_out  <<<(BM * K + 255) / 256, 256>>>((float*)d_out, BM, M, K);
}